// round 6
// baseline (speedup 1.0000x reference)
#include <cuda_runtime.h>
#include <cuda_bf16.h>
#include <cstdint>

// Problem constants
#define N_ROWS 16384
#define D_IN   1024
#define D_OUT  512
#define N_EXP  8

// GEMM tiling
#define BM 128
#define BN 128
#define KC 32                           // K elems per chunk
#define NCHUNK (D_IN / KC)              // 32
#define NSTAGE 3
#define MAX_TILES (N_ROWS / BM + N_EXP) // 136

// SMEM stage layout: 4 buffers (Ahi, Alo, Bhi, Blo), each 128 rows x 80B
#define ROWB 80
#define BUFB (128 * ROWB)               // 10240
#define STG  (4 * BUFB)                 // 40960
#define SMEM_TOTAL (NSTAGE * STG)       // 122880

// ---------------- device scratch ------------------------------------------
__device__ int g_cnt[N_EXP];
__device__ int g_cur[N_EXP];
__device__ int g_off[N_EXP + 1];
__device__ int g_perm[N_ROWS];
__device__ int g_tile_e[MAX_TILES];
__device__ int g_tile_r[MAX_TILES];
__device__ __nv_bfloat16 g_xhi[N_ROWS * D_IN];
__device__ __nv_bfloat16 g_xlo[N_ROWS * D_IN];
__device__ __nv_bfloat16 g_whi[N_EXP * D_OUT * D_IN];
__device__ __nv_bfloat16 g_wlo[N_EXP * D_OUT * D_IN];

// ---------------- PTX helpers ----------------------------------------------
__device__ __forceinline__ uint32_t smem_u32(const void* p) {
    uint32_t a;
    asm("{ .reg .u64 t; cvta.to.shared.u64 t, %1; cvt.u32.u64 %0, t; }" : "=r"(a) : "l"(p));
    return a;
}
__device__ __forceinline__ void cp16(uint32_t dst, const void* src, bool ok) {
    int sz = ok ? 16 : 0;
    asm volatile("cp.async.cg.shared.global [%0], [%1], 16, %2;" :: "r"(dst), "l"(src), "r"(sz));
}
#define CP_COMMIT() asm volatile("cp.async.commit_group;" ::: "memory")
#define CP_WAIT(n)  asm volatile("cp.async.wait_group %0;" :: "n"(n) : "memory")

__device__ __forceinline__ void ldsm4(uint32_t* r, uint32_t a) {
    asm volatile("ldmatrix.sync.aligned.m8n8.x4.shared.b16 {%0,%1,%2,%3}, [%4];"
                 : "=r"(r[0]), "=r"(r[1]), "=r"(r[2]), "=r"(r[3]) : "r"(a));
}
__device__ __forceinline__ void mma16816(float* c, const uint32_t* a, uint32_t b0, uint32_t b1) {
    asm volatile("mma.sync.aligned.m16n8k16.row.col.f32.bf16.bf16.f32 "
                 "{%0,%1,%2,%3}, {%4,%5,%6,%7}, {%8,%9}, {%0,%1,%2,%3};"
                 : "+f"(c[0]), "+f"(c[1]), "+f"(c[2]), "+f"(c[3])
                 : "r"(a[0]), "r"(a[1]), "r"(a[2]), "r"(a[3]), "r"(b0), "r"(b1));
}

// ---------------- bucketing -------------------------------------------------
__global__ void k_zero() {
    int t = threadIdx.x;
    if (t < N_EXP) { g_cnt[t] = 0; g_cur[t] = 0; }
}
__global__ void k_hist(const int* __restrict__ idx) {
    int i = blockIdx.x * blockDim.x + threadIdx.x;
    if (i < N_ROWS) atomicAdd(&g_cnt[idx[i]], 1);
}
__global__ void k_scan() {
    int off = 0, t = 0;
    for (int e = 0; e < N_EXP; ++e) {
        g_off[e] = off;
        int c = g_cnt[e];
        for (int r = 0; r < c; r += BM) { g_tile_e[t] = e; g_tile_r[t] = off + r; ++t; }
        off += c;
    }
    g_off[N_EXP] = off;
    for (; t < MAX_TILES; ++t) g_tile_e[t] = -1;
}
__global__ void k_scatter(const int* __restrict__ idx) {
    int i = blockIdx.x * blockDim.x + threadIdx.x;
    if (i < N_ROWS) {
        int e = idx[i];
        g_perm[g_off[e] + atomicAdd(&g_cur[e], 1)] = i;
    }
}

// ---------------- hi/lo bf16 conversion (x gathered via perm) ---------------
__device__ __forceinline__ void split4(float4 v, ushort4& h, ushort4& l) {
    __nv_bfloat16 h0 = __float2bfloat16_rn(v.x), h1 = __float2bfloat16_rn(v.y);
    __nv_bfloat16 h2 = __float2bfloat16_rn(v.z), h3 = __float2bfloat16_rn(v.w);
    __nv_bfloat16 l0 = __float2bfloat16_rn(v.x - __bfloat162float(h0));
    __nv_bfloat16 l1 = __float2bfloat16_rn(v.y - __bfloat162float(h1));
    __nv_bfloat16 l2 = __float2bfloat16_rn(v.z - __bfloat162float(h2));
    __nv_bfloat16 l3 = __float2bfloat16_rn(v.w - __bfloat162float(h3));
    h = make_ushort4(__bfloat16_as_ushort(h0), __bfloat16_as_ushort(h1),
                     __bfloat16_as_ushort(h2), __bfloat16_as_ushort(h3));
    l = make_ushort4(__bfloat16_as_ushort(l0), __bfloat16_as_ushort(l1),
                     __bfloat16_as_ushort(l2), __bfloat16_as_ushort(l3));
}
__global__ void k_convert_x(const float* __restrict__ x) {
    int p = blockIdx.x;
    int src = g_perm[p];
    int t = threadIdx.x;
    float4 v = ((const float4*)(x + (size_t)src * D_IN))[t];
    ushort4 h, l;
    split4(v, h, l);
    ((ushort4*)(g_xhi + (size_t)p * D_IN))[t] = h;
    ((ushort4*)(g_xlo + (size_t)p * D_IN))[t] = l;
}
__global__ void k_convert_w(const float* __restrict__ W) {
    int r = blockIdx.x;
    int t = threadIdx.x;
    float4 v = ((const float4*)(W + (size_t)r * D_IN))[t];
    ushort4 h, l;
    split4(v, h, l);
    ((ushort4*)(g_whi + (size_t)r * D_IN))[t] = h;
    ((ushort4*)(g_wlo + (size_t)r * D_IN))[t] = l;
}

// ---------------- grouped GEMM (mma.sync bf16 x3 split) ---------------------
__device__ __forceinline__ void load_stage(uint32_t sb, int s, int row0, int e,
                                           int n0, int k0) {
    const int tid = threadIdx.x;
    const uint32_t st = sb + s * STG;
    #pragma unroll
    for (int it = 0; it < 8; ++it) {
        const int id  = tid + it * 256;     // 0..2047
        const int buf = id >> 9;            // 0:Ahi 1:Alo 2:Bhi 3:Blo
        const int rem = id & 511;
        const int r   = rem >> 2;           // row 0..127
        const int c   = rem & 3;            // 16B chunk 0..3
        const uint32_t dst = st + buf * BUFB + r * ROWB + c * 16;
        const __nv_bfloat16* src;
        bool ok = true;
        if (buf < 2) {
            const int gr = row0 + r;
            ok = gr < N_ROWS;
            src = (buf == 0 ? g_xhi : g_xlo) + (size_t)(ok ? gr : 0) * D_IN + k0 + c * 8;
        } else {
            src = (buf == 2 ? g_whi : g_wlo)
                + (size_t)(e * D_OUT + n0 + r) * D_IN + k0 + c * 8;
        }
        cp16(dst, src, ok);
    }
}

__global__ void __launch_bounds__(256, 1) k_gemm(const float* __restrict__ b,
                                                 float* __restrict__ y) {
    const int e = g_tile_e[blockIdx.x];
    if (e < 0) return;
    const int row0    = g_tile_r[blockIdx.x];
    const int row_end = g_off[e + 1];
    const int n0      = blockIdx.y * BN;

    extern __shared__ char smem[];
    const uint32_t sb = smem_u32(smem);

    const int tid    = threadIdx.x;
    const int lane   = tid & 31;
    const int warp   = tid >> 5;
    const int warp_m = warp >> 2;       // 0..1 (64 rows each)
    const int warp_n = warp & 3;        // 0..3 (32 cols each)

    float acc[4][4][4];
    #pragma unroll
    for (int i = 0; i < 4; ++i)
        #pragma unroll
        for (int j = 0; j < 4; ++j)
            #pragma unroll
            for (int k = 0; k < 4; ++k) acc[i][j][k] = 0.f;

    // ldmatrix base offsets (within a stage)
    const uint32_t a_row  = warp_m * 64 + (lane & 15);
    const uint32_t a_koff = (lane >> 4) * 16;                  // bytes
    const uint32_t b_row  = warp_n * 32 + (lane & 7) + ((lane >> 4) & 1) * 8;
    const uint32_t b_koff = ((lane >> 3) & 1) * 16;            // bytes

    load_stage(sb, 0, row0, e, n0, 0);
    CP_COMMIT();
    load_stage(sb, 1, row0, e, n0, KC);
    CP_COMMIT();

    int s = 0;
    for (int c = 0; c < NCHUNK; ++c) {
        CP_WAIT(1);
        __syncthreads();
        if (c + 2 < NCHUNK) load_stage(sb, (s + 2) % NSTAGE, row0, e, n0, (c + 2) * KC);
        CP_COMMIT();

        const uint32_t st = sb + s * STG;

        // double-buffered fragments across the two ks halves of the chunk
        uint32_t ah[2][4][4], al[2][4][4], bh[2][2][4], bl[2][2][4];

        // load ks=0 fragments
        #pragma unroll
        for (int mt = 0; mt < 4; ++mt) {
            const uint32_t ad = st + (a_row + mt * 16) * ROWB + a_koff;
            ldsm4(ah[0][mt], ad);
            ldsm4(al[0][mt], ad + BUFB);
        }
        #pragma unroll
        for (int nt2 = 0; nt2 < 2; ++nt2) {
            const uint32_t bd = st + 2 * BUFB + (b_row + nt2 * 16) * ROWB + b_koff;
            ldsm4(bh[0][nt2], bd);
            ldsm4(bl[0][nt2], bd + BUFB);
        }

        #pragma unroll
        for (int ks = 0; ks < 2; ++ks) {
            // prefetch next half's fragments; overlaps this half's MMA chain
            if (ks == 0) {
                #pragma unroll
                for (int mt = 0; mt < 4; ++mt) {
                    const uint32_t ad = st + (a_row + mt * 16) * ROWB + 32 + a_koff;
                    ldsm4(ah[1][mt], ad);
                    ldsm4(al[1][mt], ad + BUFB);
                }
                #pragma unroll
                for (int nt2 = 0; nt2 < 2; ++nt2) {
                    const uint32_t bd = st + 2 * BUFB + (b_row + nt2 * 16) * ROWB + 32 + b_koff;
                    ldsm4(bh[1][nt2], bd);
                    ldsm4(bl[1][nt2], bd + BUFB);
                }
            }
            // term pass 1: hi x hi (16 independent accumulators)
            #pragma unroll
            for (int mt = 0; mt < 4; ++mt)
                #pragma unroll
                for (int nt = 0; nt < 4; ++nt) {
                    const uint32_t* bp = &bh[ks][nt >> 1][(nt & 1) * 2];
                    mma16816(acc[mt][nt], ah[ks][mt], bp[0], bp[1]);
                }
            // term pass 2: lo x hi
            #pragma unroll
            for (int mt = 0; mt < 4; ++mt)
                #pragma unroll
                for (int nt = 0; nt < 4; ++nt) {
                    const uint32_t* bp = &bh[ks][nt >> 1][(nt & 1) * 2];
                    mma16816(acc[mt][nt], al[ks][mt], bp[0], bp[1]);
                }
            // term pass 3: hi x lo
            #pragma unroll
            for (int mt = 0; mt < 4; ++mt)
                #pragma unroll
                for (int nt = 0; nt < 4; ++nt) {
                    const uint32_t* bp = &bl[ks][nt >> 1][(nt & 1) * 2];
                    mma16816(acc[mt][nt], ah[ks][mt], bp[0], bp[1]);
                }
        }
        s = (s + 1) % NSTAGE;
    }

    // epilogue: +bias, scatter rows back via perm
    const int ncol = n0 + warp_n * 32 + (lane & 3) * 2;
    float2 bias[4];
    #pragma unroll
    for (int nt = 0; nt < 4; ++nt)
        bias[nt] = *(const float2*)(b + (size_t)e * D_OUT + ncol + nt * 8);

    #pragma unroll
    for (int mt = 0; mt < 4; ++mt)
        #pragma unroll
        for (int half = 0; half < 2; ++half) {
            const int sr = row0 + warp_m * 64 + mt * 16 + (lane >> 2) + half * 8;
            if (sr < row_end) {
                const int g = g_perm[sr];
                float* yp = y + (size_t)g * D_OUT + ncol;
                #pragma unroll
                for (int nt = 0; nt < 4; ++nt) {
                    float2 v;
                    v.x = acc[mt][nt][half * 2 + 0] + bias[nt].x;
                    v.y = acc[mt][nt][half * 2 + 1] + bias[nt].y;
                    *(float2*)(yp + nt * 8) = v;
                }
            }
        }
}

// ---------------- entry -----------------------------------------------------
extern "C" void kernel_launch(void* const* d_in, const int* in_sizes, int n_in,
                              void* d_out, int out_size) {
    const float* x   = (const float*)d_in[0];
    const int*   idx = (const int*)  d_in[1];
    const float* W   = (const float*)d_in[2];
    const float* b   = (const float*)d_in[3];
    float*       y   = (float*)d_out;

    cudaFuncSetAttribute(k_gemm, cudaFuncAttributeMaxDynamicSharedMemorySize, SMEM_TOTAL);

    k_zero<<<1, 32>>>();
    k_hist<<<(N_ROWS + 255) / 256, 256>>>(idx);
    k_scan<<<1, 1>>>();
    k_scatter<<<(N_ROWS + 255) / 256, 256>>>(idx);
    k_convert_x<<<N_ROWS, 256>>>(x);
    k_convert_w<<<N_EXP * D_OUT, 256>>>(W);

    dim3 grid(MAX_TILES, D_OUT / BN);
    k_gemm<<<grid, 256, SMEM_TOTAL>>>(b, y);
}